// round 1
// baseline (speedup 1.0000x reference)
#include <cuda_runtime.h>
#include <cuda_bf16.h>

// ---------------- problem constants ----------------
#define DM     1024      // D_MODEL
#define NLAYER 2
#define VOCAB  32000
#define DS     16        // D_STATE
#define DI     2048      // D_INNER
#define DR     64        // DT_RANK
#define DC     4         // D_CONV
#define BB     2
#define LL     1024
#define TT     (BB*LL)   // 2048 tokens

// ---------------- device scratch ----------------
__device__ float g_x   [TT*DM];   // residual stream
__device__ float g_xn  [TT*DM];   // normed
__device__ float g_xi  [TT*DI];
__device__ float g_res [TT*DI];
__device__ float g_u   [TT*DI];
__device__ float g_xdbl[TT*96];   // [dlt(64) | B(16) | C(16)]
__device__ float g_dlt [TT*DI];
__device__ float g_y   [TT*DI];

// ---------------- embed ----------------
__global__ void k_embed(const int* __restrict__ ids, const float* __restrict__ emb) {
    int t = blockIdx.x;
    int id = ids[t];
    for (int c = threadIdx.x; c < DM; c += blockDim.x)
        g_x[t*DM + c] = emb[id*DM + c];
}

// ---------------- rmsnorm (one block per token) ----------------
__global__ void k_rmsnorm(const float* __restrict__ x, const float* __restrict__ w,
                          float* __restrict__ out) {
    int t = blockIdx.x;
    const float* xr = x + t*DM;
    float s = 0.f;
    for (int c = threadIdx.x; c < DM; c += blockDim.x) {
        float v = xr[c];
        s += v*v;
    }
    // warp reduce
    for (int o = 16; o > 0; o >>= 1) s += __shfl_xor_sync(0xffffffffu, s, o);
    __shared__ float red[8];
    int wid = threadIdx.x >> 5, lid = threadIdx.x & 31;
    if (lid == 0) red[wid] = s;
    __syncthreads();
    if (wid == 0) {
        float v = (lid < (blockDim.x >> 5)) ? red[lid] : 0.f;
        for (int o = 4; o > 0; o >>= 1) v += __shfl_xor_sync(0xffffffffu, v, o);
        if (lid == 0) red[0] = v;
    }
    __syncthreads();
    float scale = rsqrtf(red[0] / (float)DM + 1e-5f);
    for (int c = threadIdx.x; c < DM; c += blockDim.x)
        out[t*DM + c] = xr[c] * scale * w[c];
}

// ---------------- generic SGEMM: C[M,N] = A[M,K] * B[N,K]^T (+ epilogue) ----------------
#define EPI_NONE     0
#define EPI_SOFTPLUS 1
#define EPI_RESADD   2

template<int EPI>
__global__ void k_sgemm_nt(const float* __restrict__ A, int lda,
                           const float* __restrict__ Bw, int ldb,
                           float* __restrict__ C, int ldc,
                           int M, int N, int K,
                           const float* __restrict__ R) {
    __shared__ __align__(16) float As[16][68];
    __shared__ __align__(16) float Bs[16][68];

    const int m0 = blockIdx.y * 64;
    const int n0 = blockIdx.x * 64;
    const int tx = threadIdx.x;        // 0..15
    const int ty = threadIdx.y;        // 0..15
    const int tid = ty * 16 + tx;
    const int kk_ld = tid & 15;        // k within tile for loads
    const int rr_ld = tid >> 4;        // row within tile for loads

    float acc[4][4];
    #pragma unroll
    for (int i = 0; i < 4; i++)
        #pragma unroll
        for (int j = 0; j < 4; j++) acc[i][j] = 0.f;

    for (int k0 = 0; k0 < K; k0 += 16) {
        #pragma unroll
        for (int i = 0; i < 4; i++) {
            int m = m0 + rr_ld + i*16;
            As[kk_ld][rr_ld + i*16] = (m < M) ? A[(size_t)m*lda + k0 + kk_ld] : 0.f;
            int n = n0 + rr_ld + i*16;
            Bs[kk_ld][rr_ld + i*16] = (n < N) ? Bw[(size_t)n*ldb + k0 + kk_ld] : 0.f;
        }
        __syncthreads();
        #pragma unroll
        for (int kk = 0; kk < 16; kk++) {
            float4 a = *(const float4*)&As[kk][ty*4];
            float4 b = *(const float4*)&Bs[kk][tx*4];
            float av[4] = {a.x, a.y, a.z, a.w};
            float bv[4] = {b.x, b.y, b.z, b.w};
            #pragma unroll
            for (int i = 0; i < 4; i++)
                #pragma unroll
                for (int j = 0; j < 4; j++)
                    acc[i][j] = fmaf(av[i], bv[j], acc[i][j]);
        }
        __syncthreads();
    }

    #pragma unroll
    for (int i = 0; i < 4; i++) {
        int m = m0 + ty*4 + i;
        if (m >= M) continue;
        #pragma unroll
        for (int j = 0; j < 4; j++) {
            int n = n0 + tx*4 + j;
            if (n >= N) continue;
            float v = acc[i][j];
            if (EPI == EPI_SOFTPLUS) v = (v > 20.f) ? v : log1pf(expf(v));
            if (EPI == EPI_RESADD)   v += R[(size_t)m*ldc + n];
            C[(size_t)m*ldc + n] = v;
        }
    }
}

// ---------------- depthwise causal conv (width 4) + bias + SiLU ----------------
__global__ void k_conv_silu(const float* __restrict__ cw, const float* __restrict__ cb) {
    int idx = blockIdx.x * blockDim.x + threadIdx.x;
    if (idx >= TT*DI) return;
    int d = idx % DI;
    int l = (idx / DI) % LL;
    int b = idx / (DI*LL);
    float acc = cb[d];
    #pragma unroll
    for (int j = 0; j < DC; j++) {
        int ll = l - (DC-1) + j;
        if (ll >= 0) acc = fmaf(cw[d*DC + j], g_xi[((size_t)b*LL + ll)*DI + d], acc);
    }
    g_u[idx] = acc / (1.f + __expf(-acc));
}

// ---------------- selective scan + gate ----------------
// 16 lanes per (b,d) channel; each lane owns one state n. Block = 256 thr = 16 channels.
__global__ void k_scan(const float* __restrict__ A_log, const float* __restrict__ Dp) {
    int lane = threadIdx.x & 15;            // state index n
    int grp  = threadIdx.x >> 4;            // channel within block
    int ch   = blockIdx.x * 16 + grp;       // 0..B*DI-1
    int b = ch / DI, d = ch % DI;

    float An = -__expf(A_log[d*DS + lane]);
    float Dv = Dp[d];
    float xs = 0.f;

    for (int l = 0; l < LL; l++) {
        int tok = b*LL + l;
        float dlt = g_dlt[(size_t)tok*DI + d];
        float uu  = g_u  [(size_t)tok*DI + d];
        float Bn  = g_xdbl[(size_t)tok*96 + 64 + lane];
        float Cn  = g_xdbl[(size_t)tok*96 + 80 + lane];
        float dA  = __expf(dlt * An);
        xs = fmaf(dA, xs, dlt * uu * Bn);
        float yv = xs * Cn;
        yv += __shfl_xor_sync(0xffffffffu, yv, 8);
        yv += __shfl_xor_sync(0xffffffffu, yv, 4);
        yv += __shfl_xor_sync(0xffffffffu, yv, 2);
        yv += __shfl_xor_sync(0xffffffffu, yv, 1);
        if (lane == 0) {
            float r = g_res[(size_t)tok*DI + d];
            float gate = r / (1.f + __expf(-r));
            g_y[(size_t)tok*DI + d] = (yv + uu * Dv) * gate;
        }
    }
}

// ---------------- launch ----------------
extern "C" void kernel_launch(void* const* d_in, const int* in_sizes, int n_in,
                              void* d_out, int out_size) {
    const int*   ids      = (const int*)  d_in[0];
    const float* emb      = (const float*)d_in[1];
    const float* norm_f_w = (const float*)d_in[2];
    const float* W_in_l   = (const float*)d_in[3];
    const float* W_in_r   = (const float*)d_in[4];
    const float* conv_w   = (const float*)d_in[5];
    const float* conv_b   = (const float*)d_in[6];
    const float* W_x      = (const float*)d_in[7];
    const float* W_dt     = (const float*)d_in[8];
    const float* A_log    = (const float*)d_in[9];
    const float* Dp       = (const float*)d_in[10];
    const float* W_out    = (const float*)d_in[11];
    const float* norm_w   = (const float*)d_in[12];
    float* out = (float*)d_out;

    float *p_x, *p_xn, *p_xi, *p_res, *p_u, *p_xdbl, *p_dlt, *p_y;
    cudaGetSymbolAddress((void**)&p_x,    g_x);
    cudaGetSymbolAddress((void**)&p_xn,   g_xn);
    cudaGetSymbolAddress((void**)&p_xi,   g_xi);
    cudaGetSymbolAddress((void**)&p_res,  g_res);
    cudaGetSymbolAddress((void**)&p_u,    g_u);
    cudaGetSymbolAddress((void**)&p_xdbl, g_xdbl);
    cudaGetSymbolAddress((void**)&p_dlt,  g_dlt);
    cudaGetSymbolAddress((void**)&p_y,    g_y);

    dim3 thr16(16, 16);

    k_embed<<<TT, 256>>>(ids, emb);

    for (int i = 0; i < NLAYER; i++) {
        const float* Wl  = W_in_l + (size_t)i*DI*DM;
        const float* Wr  = W_in_r + (size_t)i*DI*DM;
        const float* cw  = conv_w + (size_t)i*DI*DC;
        const float* cb  = conv_b + (size_t)i*DI;
        const float* Wx  = W_x    + (size_t)i*(DR+2*DS)*DI;
        const float* Wdt = W_dt   + (size_t)i*DI*DR;
        const float* Al  = A_log  + (size_t)i*DI*DS;
        const float* Dpi = Dp     + (size_t)i*DI;
        const float* Wo  = W_out  + (size_t)i*DM*DI;
        const float* nw  = norm_w + (size_t)i*DM;

        k_rmsnorm<<<TT, 256>>>(p_x, nw, p_xn);

        // xi = xn @ Wl^T   (2048 x 2048, K=1024)
        k_sgemm_nt<EPI_NONE><<<dim3(DI/64, TT/64), thr16>>>(
            p_xn, DM, Wl, DM, p_xi, DI, TT, DI, DM, nullptr);
        // res = xn @ Wr^T
        k_sgemm_nt<EPI_NONE><<<dim3(DI/64, TT/64), thr16>>>(
            p_xn, DM, Wr, DM, p_res, DI, TT, DI, DM, nullptr);

        k_conv_silu<<<(TT*DI + 255)/256, 256>>>(cw, cb);

        // x_dbl = u @ Wx^T  (2048 x 96, K=2048)
        k_sgemm_nt<EPI_NONE><<<dim3((96+63)/64, TT/64), thr16>>>(
            p_u, DI, Wx, DI, p_xdbl, 96, TT, 96, DI, nullptr);

        // delta = softplus(x_dbl[:, :64] @ Wdt^T)  (2048 x 2048, K=64)
        k_sgemm_nt<EPI_SOFTPLUS><<<dim3(DI/64, TT/64), thr16>>>(
            p_xdbl, 96, Wdt, DR, p_dlt, DI, TT, DI, DR, nullptr);

        k_scan<<<(BB*DI)/16, 256>>>(Al, Dpi);

        // x = y @ Wo^T + x  (2048 x 1024, K=2048)
        k_sgemm_nt<EPI_RESADD><<<dim3(DM/64, TT/64), thr16>>>(
            p_y, DI, Wo, DI, p_x, DM, TT, DM, DI, p_x);
    }

    // final norm + logits
    k_rmsnorm<<<TT, 256>>>(p_x, norm_f_w, p_xn);
    k_sgemm_nt<EPI_NONE><<<dim3(VOCAB/64, TT/64), thr16>>>(
        p_xn, DM, emb, DM, out, VOCAB, TT, VOCAB, DM, nullptr);
}

// round 3
// speedup vs baseline: 1.9526x; 1.9526x over previous
#include <cuda_runtime.h>
#include <cuda_bf16.h>
#include <cstdint>

// ---------------- problem constants ----------------
#define DM     1024
#define NLAYER 2
#define VOCAB  32000
#define DS     16
#define DI     2048
#define DR     64
#define DC     4
#define BB     2
#define LL     1024
#define TT     (BB*LL)

// ---------------- device scratch (fp32) ----------------
__device__ float g_x   [TT*DM];
__device__ float g_xi  [TT*DI];
__device__ float g_res [TT*DI];
__device__ float g_u   [TT*DI];
__device__ float g_xdbl[TT*96];
__device__ float g_dlt [TT*DI];

// ---------------- split bf16 buffers (hi + lo) ----------------
__device__ __nv_bfloat16 g_emb_h[VOCAB*DM], g_emb_l[VOCAB*DM];
__device__ __nv_bfloat16 g_xn_h [TT*DM],    g_xn_l [TT*DM];
__device__ __nv_bfloat16 g_u_h  [TT*DI],    g_u_l  [TT*DI];
__device__ __nv_bfloat16 g_xd_h [TT*96],    g_xd_l [TT*96];
__device__ __nv_bfloat16 g_y_h  [TT*DI],    g_y_l  [TT*DI];
__device__ __nv_bfloat16 g_w_h  [DI*DM],    g_w_l  [DI*DM];   // reused per weight

// ---------------- helpers ----------------
static __device__ __forceinline__ uint32_t s2u(const void* p) {
    uint32_t a;
    asm("{ .reg .u64 t; cvta.to.shared.u64 t, %1; cvt.u32.u64 %0, t; }" : "=r"(a) : "l"(p));
    return a;
}
static __device__ __forceinline__ void cp16(uint32_t s, const void* g, bool pred) {
    int sz = pred ? 16 : 0;
    asm volatile("cp.async.cg.shared.global [%0], [%1], 16, %2;" :: "r"(s), "l"(g), "r"(sz));
}
#define CP_COMMIT() asm volatile("cp.async.commit_group;" ::: "memory")
#define CP_WAIT1()  asm volatile("cp.async.wait_group 1;"  ::: "memory")

#define LDSM4(r, addr) asm volatile( \
    "ldmatrix.sync.aligned.m8n8.x4.shared.b16 {%0,%1,%2,%3}, [%4];" \
    : "=r"((r)[0]),"=r"((r)[1]),"=r"((r)[2]),"=r"((r)[3]) : "r"(addr))
#define LDSM2(r, addr) asm volatile( \
    "ldmatrix.sync.aligned.m8n8.x2.shared.b16 {%0,%1}, [%2];" \
    : "=r"((r)[0]),"=r"((r)[1]) : "r"(addr))
#define MMA(d, a, b) asm volatile( \
    "mma.sync.aligned.m16n8k16.row.col.f32.bf16.bf16.f32 " \
    "{%0,%1,%2,%3},{%4,%5,%6,%7},{%8,%9},{%0,%1,%2,%3};" \
    : "+f"((d)[0]),"+f"((d)[1]),"+f"((d)[2]),"+f"((d)[3]) \
    : "r"((a)[0]),"r"((a)[1]),"r"((a)[2]),"r"((a)[3]),"r"((b)[0]),"r"((b)[1]))

// ---------------- embed ----------------
__global__ void k_embed(const int* __restrict__ ids, const float* __restrict__ emb) {
    int t = blockIdx.x;
    int id = ids[t];
    for (int c = threadIdx.x; c < DM; c += blockDim.x)
        g_x[t*DM + c] = emb[id*DM + c];
}

// ---------------- rmsnorm -> split bf16 ----------------
__global__ void k_rmsnorm(const float* __restrict__ x, const float* __restrict__ w,
                          __nv_bfloat16* __restrict__ oh, __nv_bfloat16* __restrict__ ol) {
    int t = blockIdx.x;
    const float* xr = x + t*DM;
    float s = 0.f;
    for (int c = threadIdx.x; c < DM; c += blockDim.x) { float v = xr[c]; s += v*v; }
    for (int o = 16; o > 0; o >>= 1) s += __shfl_xor_sync(0xffffffffu, s, o);
    __shared__ float red[8];
    int wid = threadIdx.x >> 5, lid = threadIdx.x & 31;
    if (lid == 0) red[wid] = s;
    __syncthreads();
    if (wid == 0) {
        float v = (lid < (blockDim.x >> 5)) ? red[lid] : 0.f;
        for (int o = 4; o > 0; o >>= 1) v += __shfl_xor_sync(0xffffffffu, v, o);
        if (lid == 0) red[0] = v;
    }
    __syncthreads();
    float scale = rsqrtf(red[0] / (float)DM + 1e-5f);
    for (int c = threadIdx.x; c < DM; c += blockDim.x) {
        float v = xr[c] * scale * w[c];
        __nv_bfloat16 h = __float2bfloat16(v);
        oh[t*DM + c] = h;
        ol[t*DM + c] = __float2bfloat16(v - __bfloat162float(h));
    }
}

// ---------------- fp32 -> (hi, lo) bf16 split ----------------
__global__ void k_split(const float* __restrict__ x, __nv_bfloat16* __restrict__ h,
                        __nv_bfloat16* __restrict__ l, int n) {
    int i = blockIdx.x * blockDim.x + threadIdx.x;
    if (i < n) {
        float v = x[i];
        __nv_bfloat16 hh = __float2bfloat16(v);
        h[i] = hh;
        l[i] = __float2bfloat16(v - __bfloat162float(hh));
    }
}

// ---------------- HMMA GEMM: C[M,N] = A[M,K] @ B[N,K]^T, bf16x3 split ----------------
#define EPI_NONE     0
#define EPI_SOFTPLUS 1
#define EPI_RESADD   2

#define TILE_B   8192          // 128 rows x 64 bytes
#define OFF_AH   0
#define OFF_AL   (1*TILE_B)
#define OFF_BH   (2*TILE_B)
#define OFF_BL   (3*TILE_B)
#define STAGE_B  (4*TILE_B)    // 32 KB
#define SMEM_DYN (2*STAGE_B)   // 64 KB

// swizzle: 16B chunk c of row r -> c ^ ((r>>1)&3)
__device__ __forceinline__ void load_stage(uint32_t sbase,
        const __nv_bfloat16* __restrict__ Ah, const __nv_bfloat16* __restrict__ Al,
        int lda, int m0,
        const __nv_bfloat16* __restrict__ Bh, const __nv_bfloat16* __restrict__ Bl,
        int ldb, int n0, int N, int k0, int tid) {
    #pragma unroll
    for (int it = 0; it < 2; it++) {
        int i = tid + it*256;
        int r = i >> 2;
        int cby = (i & 3) * 16;
        uint32_t off = r*64 + (cby ^ (((r >> 1) & 3) << 4));
        size_t ga = (size_t)(m0 + r)*lda + k0 + (i & 3)*8;
        cp16(sbase + OFF_AH + off, Ah + ga, true);
        cp16(sbase + OFF_AL + off, Al + ga, true);
        bool bp = (n0 + r) < N;
        int rb = bp ? (n0 + r) : (N - 1);
        size_t gb = (size_t)rb*ldb + k0 + (i & 3)*8;
        cp16(sbase + OFF_BH + off, Bh + gb, bp);
        cp16(sbase + OFF_BL + off, Bl + gb, bp);
    }
}

template<int EPI>
__global__ void __launch_bounds__(256) k_mma(
        const __nv_bfloat16* __restrict__ Ah, const __nv_bfloat16* __restrict__ Al, int lda,
        const __nv_bfloat16* __restrict__ Bh, const __nv_bfloat16* __restrict__ Bl, int ldb,
        float* __restrict__ C, int ldc, int M, int N, int K,
        const float* __restrict__ R) {
    extern __shared__ __align__(1024) char smem[];
    const uint32_t sb = s2u(smem);
    const int tid = threadIdx.x, lane = tid & 31, wid = tid >> 5;
    const int wm = wid >> 2, wn = wid & 3;       // 2 x 4 warp grid
    const int m0 = blockIdx.x * 128, n0 = blockIdx.y * 128;

    float acc[4][4][4];
    #pragma unroll
    for (int a = 0; a < 4; a++)
        #pragma unroll
        for (int b = 0; b < 4; b++)
            #pragma unroll
            for (int c = 0; c < 4; c++) acc[a][b][c] = 0.f;

    const int NC = K / 32;
    load_stage(sb + 0*STAGE_B, Ah, Al, lda, m0, Bh, Bl, ldb, n0, N,  0, tid); CP_COMMIT();
    load_stage(sb + 1*STAGE_B, Ah, Al, lda, m0, Bh, Bl, ldb, n0, N, 32, tid); CP_COMMIT();

    const int arow = lane & 15;
    const int acb  = ((lane >> 4) & 1) * 16;
    const int brow = lane & 7;
    const int bcb  = ((lane >> 3) & 1) * 16;

    for (int c = 0; c < NC; c++) {
        CP_WAIT1();
        __syncthreads();
        uint32_t st = sb + (c & 1)*STAGE_B;
        #pragma unroll
        for (int kk = 0; kk < 2; kk++) {
            uint32_t bh[4][2], bl[4][2], ah[4][4], al[4][4];
            #pragma unroll
            for (int nt = 0; nt < 4; nt++) {
                int r = wn*32 + nt*8 + brow;
                uint32_t off = r*64 + ((kk*32 + bcb) ^ (((r >> 1) & 3) << 4));
                LDSM2(bh[nt], st + OFF_BH + off);
                LDSM2(bl[nt], st + OFF_BL + off);
            }
            #pragma unroll
            for (int mt = 0; mt < 4; mt++) {
                int r = wm*64 + mt*16 + arow;
                uint32_t off = r*64 + ((kk*32 + acb) ^ (((r >> 1) & 3) << 4));
                LDSM4(ah[mt], st + OFF_AH + off);
                LDSM4(al[mt], st + OFF_AL + off);
            }
            #pragma unroll
            for (int mt = 0; mt < 4; mt++)
                #pragma unroll
                for (int nt = 0; nt < 4; nt++) {
                    MMA(acc[mt][nt], ah[mt], bh[nt]);
                    MMA(acc[mt][nt], ah[mt], bl[nt]);
                    MMA(acc[mt][nt], al[mt], bh[nt]);
                }
        }
        __syncthreads();
        if (c + 2 < NC)
            load_stage(sb + (c & 1)*STAGE_B, Ah, Al, lda, m0, Bh, Bl, ldb, n0, N,
                       (c + 2)*32, tid);
        CP_COMMIT();
    }

    // epilogue
    #pragma unroll
    for (int mt = 0; mt < 4; mt++) {
        #pragma unroll
        for (int nt = 0; nt < 4; nt++) {
            int row = m0 + wm*64 + mt*16 + (lane >> 2);
            int col = n0 + wn*32 + nt*8 + (lane & 3)*2;
            if (col < N) {
                #pragma unroll
                for (int h = 0; h < 2; h++) {
                    int rr = row + h*8;
                    float v0 = acc[mt][nt][2*h + 0];
                    float v1 = acc[mt][nt][2*h + 1];
                    if (EPI == EPI_SOFTPLUS) {
                        v0 = (v0 > 20.f) ? v0 : log1pf(expf(v0));
                        v1 = (v1 > 20.f) ? v1 : log1pf(expf(v1));
                    }
                    if (EPI == EPI_RESADD) {
                        v0 += R[(size_t)rr*ldc + col];
                        v1 += R[(size_t)rr*ldc + col + 1];
                    }
                    *reinterpret_cast<float2*>(&C[(size_t)rr*ldc + col]) = make_float2(v0, v1);
                }
            }
        }
    }
}

// ---------------- depthwise causal conv + bias + SiLU -> u fp32 + split ----------------
__global__ void k_conv_silu(const float* __restrict__ cw, const float* __restrict__ cb) {
    int idx = blockIdx.x * blockDim.x + threadIdx.x;
    if (idx >= TT*DI) return;
    int d = idx % DI;
    int l = (idx / DI) % LL;
    int b = idx / (DI*LL);
    float acc = cb[d];
    #pragma unroll
    for (int j = 0; j < DC; j++) {
        int ll = l - (DC-1) + j;
        if (ll >= 0) acc = fmaf(cw[d*DC + j], g_xi[((size_t)b*LL + ll)*DI + d], acc);
    }
    float s = acc / (1.f + __expf(-acc));
    g_u[idx] = s;
    __nv_bfloat16 h = __float2bfloat16(s);
    g_u_h[idx] = h;
    g_u_l[idx] = __float2bfloat16(s - __bfloat162float(h));
}

// ---------------- selective scan + gate -> y split ----------------
__global__ void k_scan(const float* __restrict__ A_log, const float* __restrict__ Dp) {
    int lane = threadIdx.x & 15;
    int grp  = threadIdx.x >> 4;
    int ch   = blockIdx.x * 16 + grp;
    int b = ch / DI, d = ch % DI;

    float An = -__expf(A_log[d*DS + lane]);
    float Dv = Dp[d];
    float xs = 0.f;

    for (int l = 0; l < LL; l++) {
        int tok = b*LL + l;
        float dlt = g_dlt[(size_t)tok*DI + d];
        float uu  = g_u  [(size_t)tok*DI + d];
        float Bn  = g_xdbl[(size_t)tok*96 + 64 + lane];
        float Cn  = g_xdbl[(size_t)tok*96 + 80 + lane];
        float dA  = __expf(dlt * An);
        xs = fmaf(dA, xs, dlt * uu * Bn);
        float yv = xs * Cn;
        yv += __shfl_xor_sync(0xffffffffu, yv, 8);
        yv += __shfl_xor_sync(0xffffffffu, yv, 4);
        yv += __shfl_xor_sync(0xffffffffu, yv, 2);
        yv += __shfl_xor_sync(0xffffffffu, yv, 1);
        if (lane == 0) {
            float r = g_res[(size_t)tok*DI + d];
            float gate = r / (1.f + __expf(-r));
            float v = (yv + uu * Dv) * gate;
            __nv_bfloat16 h = __float2bfloat16(v);
            g_y_h[(size_t)tok*DI + d] = h;
            g_y_l[(size_t)tok*DI + d] = __float2bfloat16(v - __bfloat162float(h));
        }
    }
}

// ---------------- launch ----------------
extern "C" void kernel_launch(void* const* d_in, const int* in_sizes, int n_in,
                              void* d_out, int out_size) {
    const int*   ids      = (const int*)  d_in[0];
    const float* emb      = (const float*)d_in[1];
    const float* norm_f_w = (const float*)d_in[2];
    const float* W_in_l   = (const float*)d_in[3];
    const float* W_in_r   = (const float*)d_in[4];
    const float* conv_w   = (const float*)d_in[5];
    const float* conv_b   = (const float*)d_in[6];
    const float* W_x      = (const float*)d_in[7];
    const float* W_dt     = (const float*)d_in[8];
    const float* A_log    = (const float*)d_in[9];
    const float* Dp       = (const float*)d_in[10];
    const float* W_out    = (const float*)d_in[11];
    const float* norm_w   = (const float*)d_in[12];
    float* out = (float*)d_out;

    float *p_x, *p_xi, *p_res, *p_u, *p_xdbl, *p_dlt;
    cudaGetSymbolAddress((void**)&p_x,    g_x);
    cudaGetSymbolAddress((void**)&p_xi,   g_xi);
    cudaGetSymbolAddress((void**)&p_res,  g_res);
    cudaGetSymbolAddress((void**)&p_u,    g_u);
    cudaGetSymbolAddress((void**)&p_xdbl, g_xdbl);
    cudaGetSymbolAddress((void**)&p_dlt,  g_dlt);

    __nv_bfloat16 *p_eh, *p_el, *p_xnh, *p_xnl, *p_uh, *p_ul, *p_xdh, *p_xdl, *p_yh, *p_yl, *p_wh, *p_wl;
    cudaGetSymbolAddress((void**)&p_eh,  g_emb_h);
    cudaGetSymbolAddress((void**)&p_el,  g_emb_l);
    cudaGetSymbolAddress((void**)&p_xnh, g_xn_h);
    cudaGetSymbolAddress((void**)&p_xnl, g_xn_l);
    cudaGetSymbolAddress((void**)&p_uh,  g_u_h);
    cudaGetSymbolAddress((void**)&p_ul,  g_u_l);
    cudaGetSymbolAddress((void**)&p_xdh, g_xd_h);
    cudaGetSymbolAddress((void**)&p_xdl, g_xd_l);
    cudaGetSymbolAddress((void**)&p_yh,  g_y_h);
    cudaGetSymbolAddress((void**)&p_yl,  g_y_l);
    cudaGetSymbolAddress((void**)&p_wh,  g_w_h);
    cudaGetSymbolAddress((void**)&p_wl,  g_w_l);

    cudaFuncSetAttribute(k_mma<EPI_NONE>,     cudaFuncAttributeMaxDynamicSharedMemorySize, SMEM_DYN);
    cudaFuncSetAttribute(k_mma<EPI_SOFTPLUS>, cudaFuncAttributeMaxDynamicSharedMemorySize, SMEM_DYN);
    cudaFuncSetAttribute(k_mma<EPI_RESADD>,   cudaFuncAttributeMaxDynamicSharedMemorySize, SMEM_DYN);

    k_embed<<<TT, 256>>>(ids, emb);
    k_split<<<(VOCAB*DM + 255)/256, 256>>>(emb, p_eh, p_el, VOCAB*DM);

    for (int i = 0; i < NLAYER; i++) {
        const float* Wl  = W_in_l + (size_t)i*DI*DM;
        const float* Wr  = W_in_r + (size_t)i*DI*DM;
        const float* cw  = conv_w + (size_t)i*DI*DC;
        const float* cb  = conv_b + (size_t)i*DI;
        const float* Wx  = W_x    + (size_t)i*(DR+2*DS)*DI;
        const float* Wdt = W_dt   + (size_t)i*DI*DR;
        const float* Al  = A_log  + (size_t)i*DI*DS;
        const float* Dpi = Dp     + (size_t)i*DI;
        const float* Wo  = W_out  + (size_t)i*DM*DI;
        const float* nw  = norm_w + (size_t)i*DM;

        k_rmsnorm<<<TT, 256>>>(p_x, nw, p_xnh, p_xnl);

        // xi = xn @ Wl^T   (2048 x 2048, K=1024)
        k_split<<<(DI*DM + 255)/256, 256>>>(Wl, p_wh, p_wl, DI*DM);
        k_mma<EPI_NONE><<<dim3(TT/128, DI/128), 256, SMEM_DYN>>>(
            p_xnh, p_xnl, DM, p_wh, p_wl, DM, p_xi, DI, TT, DI, DM, nullptr);

        // res = xn @ Wr^T
        k_split<<<(DI*DM + 255)/256, 256>>>(Wr, p_wh, p_wl, DI*DM);
        k_mma<EPI_NONE><<<dim3(TT/128, DI/128), 256, SMEM_DYN>>>(
            p_xnh, p_xnl, DM, p_wh, p_wl, DM, p_res, DI, TT, DI, DM, nullptr);

        k_conv_silu<<<(TT*DI + 255)/256, 256>>>(cw, cb);

        // x_dbl = u @ Wx^T  (2048 x 96, K=2048)
        k_split<<<(96*DI + 255)/256, 256>>>(Wx, p_wh, p_wl, 96*DI);
        k_mma<EPI_NONE><<<dim3(TT/128, 1), 256, SMEM_DYN>>>(
            p_uh, p_ul, DI, p_wh, p_wl, DI, p_xdbl, 96, TT, 96, DI, nullptr);

        k_split<<<(TT*96 + 255)/256, 256>>>(p_xdbl, p_xdh, p_xdl, TT*96);

        // delta = softplus(x_dbl[:, :64] @ Wdt^T)  (2048 x 2048, K=64)
        k_split<<<(DI*DR + 255)/256, 256>>>(Wdt, p_wh, p_wl, DI*DR);
        k_mma<EPI_SOFTPLUS><<<dim3(TT/128, DI/128), 256, SMEM_DYN>>>(
            p_xdh, p_xdl, 96, p_wh, p_wl, DR, p_dlt, DI, TT, DI, DR, nullptr);

        k_scan<<<(BB*DI)/16, 256>>>(Al, Dpi);

        // x = y @ Wo^T + x  (2048 x 1024, K=2048)
        k_split<<<(DM*DI + 255)/256, 256>>>(Wo, p_wh, p_wl, DM*DI);
        k_mma<EPI_RESADD><<<dim3(TT/128, DM/128), 256, SMEM_DYN>>>(
            p_yh, p_yl, DI, p_wh, p_wl, DI, p_x, DM, TT, DM, DI, p_x);
    }

    // final norm + logits (2048 x 32000, K=1024)
    k_rmsnorm<<<TT, 256>>>(p_x, norm_f_w, p_xnh, p_xnl);
    k_mma<EPI_NONE><<<dim3(TT/128, VOCAB/128), 256, SMEM_DYN>>>(
        p_xnh, p_xnl, DM, p_eh, p_el, DM, out, VOCAB, TT, VOCAB, DM, nullptr);
}

// round 4
// speedup vs baseline: 2.1492x; 1.1007x over previous
#include <cuda_runtime.h>
#include <cuda_bf16.h>
#include <cstdint>

// ---------------- problem constants ----------------
#define DM     1024
#define NLAYER 2
#define VOCAB  32000
#define DS     16
#define DI     2048
#define DR     64
#define DC     4
#define BB     2
#define LL     1024
#define TT     (BB*LL)

// ---------------- device scratch (fp32) ----------------
__device__ float g_x   [TT*DM];
__device__ float g_xi  [TT*DI];
__device__ float g_res [TT*DI];
__device__ float g_u   [TT*DI];
__device__ float g_xdbl[TT*96];
__device__ float g_dlt [TT*DI];

// ---------------- split bf16 buffers (hi + lo) ----------------
__device__ __nv_bfloat16 g_emb_h[VOCAB*DM], g_emb_l[VOCAB*DM];
__device__ __nv_bfloat16 g_xn_h [TT*DM],    g_xn_l [TT*DM];
__device__ __nv_bfloat16 g_u_h  [TT*DI],    g_u_l  [TT*DI];
__device__ __nv_bfloat16 g_xd_h [TT*96],    g_xd_l [TT*96];
__device__ __nv_bfloat16 g_y_h  [TT*DI],    g_y_l  [TT*DI];
__device__ __nv_bfloat16 g_w_h  [DI*DM],    g_w_l  [DI*DM];

// ---------------- helpers ----------------
static __device__ __forceinline__ uint32_t s2u(const void* p) {
    uint32_t a;
    asm("{ .reg .u64 t; cvta.to.shared.u64 t, %1; cvt.u32.u64 %0, t; }" : "=r"(a) : "l"(p));
    return a;
}
static __device__ __forceinline__ void cp16(uint32_t s, const void* g, bool pred) {
    int sz = pred ? 16 : 0;
    asm volatile("cp.async.cg.shared.global [%0], [%1], 16, %2;" :: "r"(s), "l"(g), "r"(sz));
}
#define CP_COMMIT() asm volatile("cp.async.commit_group;" ::: "memory")
#define CP_WAIT1()  asm volatile("cp.async.wait_group 1;"  ::: "memory")

#define LDSM4(r, addr) asm volatile( \
    "ldmatrix.sync.aligned.m8n8.x4.shared.b16 {%0,%1,%2,%3}, [%4];" \
    : "=r"((r)[0]),"=r"((r)[1]),"=r"((r)[2]),"=r"((r)[3]) : "r"(addr))
#define MMA(d, a, b) asm volatile( \
    "mma.sync.aligned.m16n8k16.row.col.f32.bf16.bf16.f32 " \
    "{%0,%1,%2,%3},{%4,%5,%6,%7},{%8,%9},{%0,%1,%2,%3};" \
    : "+f"((d)[0]),"+f"((d)[1]),"+f"((d)[2]),"+f"((d)[3]) \
    : "r"((a)[0]),"r"((a)[1]),"r"((a)[2]),"r"((a)[3]),"r"((b)[0]),"r"((b)[1]))

// ---------------- embed ----------------
__global__ void k_embed(const int* __restrict__ ids, const float* __restrict__ emb) {
    int t = blockIdx.x;
    int id = ids[t];
    for (int c = threadIdx.x; c < DM; c += blockDim.x)
        g_x[t*DM + c] = emb[id*DM + c];
}

// ---------------- rmsnorm -> split bf16 ----------------
__global__ void k_rmsnorm(const float* __restrict__ x, const float* __restrict__ w,
                          __nv_bfloat16* __restrict__ oh, __nv_bfloat16* __restrict__ ol) {
    int t = blockIdx.x;
    const float* xr = x + t*DM;
    float s = 0.f;
    for (int c = threadIdx.x; c < DM; c += blockDim.x) { float v = xr[c]; s += v*v; }
    for (int o = 16; o > 0; o >>= 1) s += __shfl_xor_sync(0xffffffffu, s, o);
    __shared__ float red[8];
    int wid = threadIdx.x >> 5, lid = threadIdx.x & 31;
    if (lid == 0) red[wid] = s;
    __syncthreads();
    if (wid == 0) {
        float v = (lid < (blockDim.x >> 5)) ? red[lid] : 0.f;
        for (int o = 4; o > 0; o >>= 1) v += __shfl_xor_sync(0xffffffffu, v, o);
        if (lid == 0) red[0] = v;
    }
    __syncthreads();
    float scale = rsqrtf(red[0] / (float)DM + 1e-5f);
    for (int c = threadIdx.x; c < DM; c += blockDim.x) {
        float v = xr[c] * scale * w[c];
        __nv_bfloat16 h = __float2bfloat16(v);
        oh[t*DM + c] = h;
        ol[t*DM + c] = __float2bfloat16(v - __bfloat162float(h));
    }
}

// ---------------- fp32 -> (hi, lo) bf16 split, 4 elems/thread ----------------
__global__ void k_split(const float* __restrict__ x, __nv_bfloat16* __restrict__ h,
                        __nv_bfloat16* __restrict__ l, int n) {
    int i = (blockIdx.x * blockDim.x + threadIdx.x) * 4;
    if (i >= n) return;
    float4 v = *reinterpret_cast<const float4*>(x + i);
    __nv_bfloat16 h0 = __float2bfloat16(v.x), h1 = __float2bfloat16(v.y);
    __nv_bfloat16 h2 = __float2bfloat16(v.z), h3 = __float2bfloat16(v.w);
    __nv_bfloat162 H0, H1, L0, L1;
    H0.x = h0; H0.y = h1; H1.x = h2; H1.y = h3;
    L0.x = __float2bfloat16(v.x - __bfloat162float(h0));
    L0.y = __float2bfloat16(v.y - __bfloat162float(h1));
    L1.x = __float2bfloat16(v.z - __bfloat162float(h2));
    L1.y = __float2bfloat16(v.w - __bfloat162float(h3));
    uint2 ph = make_uint2(*reinterpret_cast<uint32_t*>(&H0), *reinterpret_cast<uint32_t*>(&H1));
    uint2 pl = make_uint2(*reinterpret_cast<uint32_t*>(&L0), *reinterpret_cast<uint32_t*>(&L1));
    *reinterpret_cast<uint2*>(h + i) = ph;
    *reinterpret_cast<uint2*>(l + i) = pl;
}

// ---------------- HMMA GEMM: C[M,N] = A[M,K] @ B[N,K]^T, bf16x3 split ----------------
#define EPI_NONE     0
#define EPI_SOFTPLUS 1
#define EPI_RESADD   2

#define TILE_B   8192          // 128 rows x 64 bytes (BK=32 bf16)
#define OFF_AH   0
#define OFF_AL   (1*TILE_B)
#define OFF_BH   (2*TILE_B)
#define OFF_BL   (3*TILE_B)
#define STAGE_B  (4*TILE_B)    // 32 KB
#define NSTAGE   3
#define SMEM_DYN (NSTAGE*STAGE_B)   // 96 KB

__device__ __forceinline__ void load_stage(uint32_t sbase,
        const __nv_bfloat16* __restrict__ Ah, const __nv_bfloat16* __restrict__ Al,
        int lda, int m0,
        const __nv_bfloat16* __restrict__ Bh, const __nv_bfloat16* __restrict__ Bl,
        int ldb, int n0, int N, int k0, int tid) {
    #pragma unroll
    for (int it = 0; it < 2; it++) {
        int i = tid + it*256;
        int r = i >> 2;
        int cby = (i & 3) * 16;
        uint32_t off = r*64 + (cby ^ (((r >> 1) & 3) << 4));
        size_t ga = (size_t)(m0 + r)*lda + k0 + (i & 3)*8;
        cp16(sbase + OFF_AH + off, Ah + ga, true);
        cp16(sbase + OFF_AL + off, Al + ga, true);
        bool bp = (n0 + r) < N;
        int rb = bp ? (n0 + r) : (N - 1);
        size_t gb = (size_t)rb*ldb + k0 + (i & 3)*8;
        cp16(sbase + OFF_BH + off, Bh + gb, bp);
        cp16(sbase + OFF_BL + off, Bl + gb, bp);
    }
}

template<int EPI>
__global__ void __launch_bounds__(256) k_mma(
        const __nv_bfloat16* __restrict__ Ah, const __nv_bfloat16* __restrict__ Al, int lda,
        const __nv_bfloat16* __restrict__ Bh, const __nv_bfloat16* __restrict__ Bl, int ldb,
        float* __restrict__ C, int ldc, int M, int N, int K,
        const float* __restrict__ R) {
    extern __shared__ __align__(1024) char smem[];
    const uint32_t sb = s2u(smem);
    const int tid = threadIdx.x, lane = tid & 31, wid = tid >> 5;
    const int wm = wid >> 2, wn = wid & 3;       // 2 x 4 warp grid
    const int m0 = blockIdx.x * 128, n0 = blockIdx.y * 128;

    float acc[4][4][4];
    #pragma unroll
    for (int a = 0; a < 4; a++)
        #pragma unroll
        for (int b = 0; b < 4; b++)
            #pragma unroll
            for (int c = 0; c < 4; c++) acc[a][b][c] = 0.f;

    const int NC = K / 32;
    load_stage(sb + 0*STAGE_B, Ah, Al, lda, m0, Bh, Bl, ldb, n0, N,  0, tid); CP_COMMIT();
    load_stage(sb + 1*STAGE_B, Ah, Al, lda, m0, Bh, Bl, ldb, n0, N, 32, tid); CP_COMMIT();

    // A addressing: 16-row fragment
    const int arow = lane & 15;
    const int acb  = ((lane >> 4) & 1) * 16;
    // B addressing for x4 (two n-tiles per ldmatrix):
    const int brow = lane & 7;
    const int bnt  = (lane >> 4) & 1;     // which tile of the pair
    const int bkh  = (lane >> 3) & 1;     // k-half (0 / +16B)

    int stage = 0;
    for (int c = 0; c < NC; c++) {
        CP_WAIT1();
        __syncthreads();
        // issue next-next stage loads BEFORE compute (overlap DRAM with MMA)
        if (c + 2 < NC) {
            int s2 = stage + 2; if (s2 >= NSTAGE) s2 -= NSTAGE;
            load_stage(sb + s2*STAGE_B, Ah, Al, lda, m0, Bh, Bl, ldb, n0, N,
                       (c + 2)*32, tid);
        }
        CP_COMMIT();

        uint32_t st = sb + stage*STAGE_B;
        #pragma unroll
        for (int kk = 0; kk < 2; kk++) {
            uint32_t bh[4][2], bl[4][2], ah[4][4], al[4][4];
            #pragma unroll
            for (int p = 0; p < 2; p++) {
                int r = wn*32 + (p*2 + bnt)*8 + brow;
                uint32_t off = r*64 + (((kk*2 + bkh)*16) ^ (((r >> 1) & 3) << 4));
                uint32_t t[4];
                LDSM4(t, st + OFF_BH + off);
                bh[2*p][0] = t[0]; bh[2*p][1] = t[1];
                bh[2*p+1][0] = t[2]; bh[2*p+1][1] = t[3];
                LDSM4(t, st + OFF_BL + off);
                bl[2*p][0] = t[0]; bl[2*p][1] = t[1];
                bl[2*p+1][0] = t[2]; bl[2*p+1][1] = t[3];
            }
            #pragma unroll
            for (int mt = 0; mt < 4; mt++) {
                int r = wm*64 + mt*16 + arow;
                uint32_t off = r*64 + ((kk*32 + acb) ^ (((r >> 1) & 3) << 4));
                LDSM4(ah[mt], st + OFF_AH + off);
                LDSM4(al[mt], st + OFF_AL + off);
            }
            // term-major: consecutive MMAs hit different accumulators
            #pragma unroll
            for (int mt = 0; mt < 4; mt++)
                #pragma unroll
                for (int nt = 0; nt < 4; nt++)
                    MMA(acc[mt][nt], ah[mt], bh[nt]);
            #pragma unroll
            for (int mt = 0; mt < 4; mt++)
                #pragma unroll
                for (int nt = 0; nt < 4; nt++)
                    MMA(acc[mt][nt], ah[mt], bl[nt]);
            #pragma unroll
            for (int mt = 0; mt < 4; mt++)
                #pragma unroll
                for (int nt = 0; nt < 4; nt++)
                    MMA(acc[mt][nt], al[mt], bh[nt]);
        }
        stage++; if (stage >= NSTAGE) stage = 0;
    }

    // epilogue
    #pragma unroll
    for (int mt = 0; mt < 4; mt++) {
        #pragma unroll
        for (int nt = 0; nt < 4; nt++) {
            int row = m0 + wm*64 + mt*16 + (lane >> 2);
            int col = n0 + wn*32 + nt*8 + (lane & 3)*2;
            if (col < N) {
                #pragma unroll
                for (int h = 0; h < 2; h++) {
                    int rr = row + h*8;
                    float v0 = acc[mt][nt][2*h + 0];
                    float v1 = acc[mt][nt][2*h + 1];
                    if (EPI == EPI_SOFTPLUS) {
                        v0 = (v0 > 20.f) ? v0 : log1pf(expf(v0));
                        v1 = (v1 > 20.f) ? v1 : log1pf(expf(v1));
                    }
                    if (EPI == EPI_RESADD) {
                        v0 += R[(size_t)rr*ldc + col];
                        v1 += R[(size_t)rr*ldc + col + 1];
                    }
                    *reinterpret_cast<float2*>(&C[(size_t)rr*ldc + col]) = make_float2(v0, v1);
                }
            }
        }
    }
}

// ---------------- depthwise causal conv + bias + SiLU -> u fp32 + split ----------------
__global__ void k_conv_silu(const float* __restrict__ cw, const float* __restrict__ cb) {
    int idx = blockIdx.x * blockDim.x + threadIdx.x;
    if (idx >= TT*DI) return;
    int d = idx % DI;
    int l = (idx / DI) % LL;
    int b = idx / (DI*LL);
    float acc = cb[d];
    #pragma unroll
    for (int j = 0; j < DC; j++) {
        int ll = l - (DC-1) + j;
        if (ll >= 0) acc = fmaf(cw[d*DC + j], g_xi[((size_t)b*LL + ll)*DI + d], acc);
    }
    float s = acc / (1.f + __expf(-acc));
    g_u[idx] = s;
    __nv_bfloat16 h = __float2bfloat16(s);
    g_u_h[idx] = h;
    g_u_l[idx] = __float2bfloat16(s - __bfloat162float(h));
}

// ---------------- selective scan + gate -> y split ----------------
__global__ void k_scan(const float* __restrict__ A_log, const float* __restrict__ Dp) {
    int lane = threadIdx.x & 15;
    int grp  = threadIdx.x >> 4;
    int ch   = blockIdx.x * 16 + grp;
    int b = ch / DI, d = ch % DI;

    float An = -__expf(A_log[d*DS + lane]);
    float Dv = Dp[d];
    float xs = 0.f;

    for (int l = 0; l < LL; l++) {
        int tok = b*LL + l;
        float dlt = g_dlt[(size_t)tok*DI + d];
        float uu  = g_u  [(size_t)tok*DI + d];
        float Bn  = g_xdbl[(size_t)tok*96 + 64 + lane];
        float Cn  = g_xdbl[(size_t)tok*96 + 80 + lane];
        float dA  = __expf(dlt * An);
        xs = fmaf(dA, xs, dlt * uu * Bn);
        float yv = xs * Cn;
        yv += __shfl_xor_sync(0xffffffffu, yv, 8);
        yv += __shfl_xor_sync(0xffffffffu, yv, 4);
        yv += __shfl_xor_sync(0xffffffffu, yv, 2);
        yv += __shfl_xor_sync(0xffffffffu, yv, 1);
        if (lane == 0) {
            float r = g_res[(size_t)tok*DI + d];
            float gate = r / (1.f + __expf(-r));
            float v = (yv + uu * Dv) * gate;
            __nv_bfloat16 h = __float2bfloat16(v);
            g_y_h[(size_t)tok*DI + d] = h;
            g_y_l[(size_t)tok*DI + d] = __float2bfloat16(v - __bfloat162float(h));
        }
    }
}

// ---------------- launch ----------------
extern "C" void kernel_launch(void* const* d_in, const int* in_sizes, int n_in,
                              void* d_out, int out_size) {
    const int*   ids      = (const int*)  d_in[0];
    const float* emb      = (const float*)d_in[1];
    const float* norm_f_w = (const float*)d_in[2];
    const float* W_in_l   = (const float*)d_in[3];
    const float* W_in_r   = (const float*)d_in[4];
    const float* conv_w   = (const float*)d_in[5];
    const float* conv_b   = (const float*)d_in[6];
    const float* W_x      = (const float*)d_in[7];
    const float* W_dt     = (const float*)d_in[8];
    const float* A_log    = (const float*)d_in[9];
    const float* Dp       = (const float*)d_in[10];
    const float* W_out    = (const float*)d_in[11];
    const float* norm_w   = (const float*)d_in[12];
    float* out = (float*)d_out;

    float *p_x, *p_xi, *p_res, *p_u, *p_xdbl, *p_dlt;
    cudaGetSymbolAddress((void**)&p_x,    g_x);
    cudaGetSymbolAddress((void**)&p_xi,   g_xi);
    cudaGetSymbolAddress((void**)&p_res,  g_res);
    cudaGetSymbolAddress((void**)&p_u,    g_u);
    cudaGetSymbolAddress((void**)&p_xdbl, g_xdbl);
    cudaGetSymbolAddress((void**)&p_dlt,  g_dlt);

    __nv_bfloat16 *p_eh, *p_el, *p_xnh, *p_xnl, *p_uh, *p_ul, *p_xdh, *p_xdl, *p_yh, *p_yl, *p_wh, *p_wl;
    cudaGetSymbolAddress((void**)&p_eh,  g_emb_h);
    cudaGetSymbolAddress((void**)&p_el,  g_emb_l);
    cudaGetSymbolAddress((void**)&p_xnh, g_xn_h);
    cudaGetSymbolAddress((void**)&p_xnl, g_xn_l);
    cudaGetSymbolAddress((void**)&p_uh,  g_u_h);
    cudaGetSymbolAddress((void**)&p_ul,  g_u_l);
    cudaGetSymbolAddress((void**)&p_xdh, g_xd_h);
    cudaGetSymbolAddress((void**)&p_xdl, g_xd_l);
    cudaGetSymbolAddress((void**)&p_yh,  g_y_h);
    cudaGetSymbolAddress((void**)&p_yl,  g_y_l);
    cudaGetSymbolAddress((void**)&p_wh,  g_w_h);
    cudaGetSymbolAddress((void**)&p_wl,  g_w_l);

    cudaFuncSetAttribute(k_mma<EPI_NONE>,     cudaFuncAttributeMaxDynamicSharedMemorySize, SMEM_DYN);
    cudaFuncSetAttribute(k_mma<EPI_SOFTPLUS>, cudaFuncAttributeMaxDynamicSharedMemorySize, SMEM_DYN);
    cudaFuncSetAttribute(k_mma<EPI_RESADD>,   cudaFuncAttributeMaxDynamicSharedMemorySize, SMEM_DYN);

    k_embed<<<TT, 256>>>(ids, emb);
    k_split<<<(VOCAB*DM/4 + 255)/256, 256>>>(emb, p_eh, p_el, VOCAB*DM);

    for (int i = 0; i < NLAYER; i++) {
        const float* Wl  = W_in_l + (size_t)i*DI*DM;
        const float* Wr  = W_in_r + (size_t)i*DI*DM;
        const float* cw  = conv_w + (size_t)i*DI*DC;
        const float* cb  = conv_b + (size_t)i*DI;
        const float* Wx  = W_x    + (size_t)i*(DR+2*DS)*DI;
        const float* Wdt = W_dt   + (size_t)i*DI*DR;
        const float* Al  = A_log  + (size_t)i*DI*DS;
        const float* Dpi = Dp     + (size_t)i*DI;
        const float* Wo  = W_out  + (size_t)i*DM*DI;
        const float* nw  = norm_w + (size_t)i*DM;

        k_rmsnorm<<<TT, 256>>>(p_x, nw, p_xnh, p_xnl);

        // xi = xn @ Wl^T   (2048 x 2048, K=1024)
        k_split<<<(DI*DM/4 + 255)/256, 256>>>(Wl, p_wh, p_wl, DI*DM);
        k_mma<EPI_NONE><<<dim3(TT/128, DI/128), 256, SMEM_DYN>>>(
            p_xnh, p_xnl, DM, p_wh, p_wl, DM, p_xi, DI, TT, DI, DM, nullptr);

        // res = xn @ Wr^T
        k_split<<<(DI*DM/4 + 255)/256, 256>>>(Wr, p_wh, p_wl, DI*DM);
        k_mma<EPI_NONE><<<dim3(TT/128, DI/128), 256, SMEM_DYN>>>(
            p_xnh, p_xnl, DM, p_wh, p_wl, DM, p_res, DI, TT, DI, DM, nullptr);

        k_conv_silu<<<(TT*DI + 255)/256, 256>>>(cw, cb);

        // x_dbl = u @ Wx^T  (2048 x 96, K=2048)
        k_split<<<(96*DI/4 + 255)/256, 256>>>(Wx, p_wh, p_wl, 96*DI);
        k_mma<EPI_NONE><<<dim3(TT/128, 1), 256, SMEM_DYN>>>(
            p_uh, p_ul, DI, p_wh, p_wl, DI, p_xdbl, 96, TT, 96, DI, nullptr);

        k_split<<<(TT*96/4 + 255)/256, 256>>>(p_xdbl, p_xdh, p_xdl, TT*96);

        // delta = softplus(x_dbl[:, :64] @ Wdt^T)  (2048 x 2048, K=64)
        k_split<<<(DI*DR/4 + 255)/256, 256>>>(Wdt, p_wh, p_wl, DI*DR);
        k_mma<EPI_SOFTPLUS><<<dim3(TT/128, DI/128), 256, SMEM_DYN>>>(
            p_xdh, p_xdl, 96, p_wh, p_wl, DR, p_dlt, DI, TT, DI, DR, nullptr);

        k_scan<<<(BB*DI)/16, 256>>>(Al, Dpi);

        // x = y @ Wo^T + x  (2048 x 1024, K=2048)
        k_split<<<(DM*DI/4 + 255)/256, 256>>>(Wo, p_wh, p_wl, DM*DI);
        k_mma<EPI_RESADD><<<dim3(TT/128, DM/128), 256, SMEM_DYN>>>(
            p_yh, p_yl, DI, p_wh, p_wl, DI, p_x, DM, TT, DM, DI, p_x);
    }

    // final norm + logits (2048 x 32000, K=1024)
    k_rmsnorm<<<TT, 256>>>(p_x, norm_f_w, p_xnh, p_xnl);
    k_mma<EPI_NONE><<<dim3(TT/128, VOCAB/128), 256, SMEM_DYN>>>(
        p_xnh, p_xnl, DM, p_eh, p_el, DM, out, VOCAB, TT, VOCAB, DM, nullptr);
}

// round 5
// speedup vs baseline: 2.4094x; 1.1211x over previous
#include <cuda_runtime.h>
#include <cuda_fp16.h>
#include <cuda_bf16.h>
#include <cstdint>

// ---------------- problem constants ----------------
#define DM     1024
#define NLAYER 2
#define VOCAB  32000
#define DS     16
#define DI     2048
#define DR     64
#define DC     4
#define BB     2
#define LL     1024
#define TT     (BB*LL)

// ---------------- device scratch (fp32) ----------------
__device__ float g_x   [TT*DM];
__device__ float g_xi  [TT*DI];
__device__ float g_res [TT*DI];
__device__ float g_u   [TT*DI];
__device__ float g_xdbl[TT*96];
__device__ float g_dlt [TT*DI];

// ---------------- fp16 buffers: A-side split (hi+lo), B-side plain ----------------
__device__ __half g_emb_f[VOCAB*DM];                 // B-side: logits weights
__device__ __half g_xn_h [TT*DM],  g_xn_l [TT*DM];   // A-side
__device__ __half g_u_h  [TT*DI],  g_u_l  [TT*DI];
__device__ __half g_xd_h [TT*96],  g_xd_l [TT*96];
__device__ __half g_y_h  [TT*DI],  g_y_l  [TT*DI];
__device__ __half g_w_f  [DI*DM];                    // B-side: reused per weight

// ---------------- helpers ----------------
static __device__ __forceinline__ uint32_t s2u(const void* p) {
    uint32_t a;
    asm("{ .reg .u64 t; cvta.to.shared.u64 t, %1; cvt.u32.u64 %0, t; }" : "=r"(a) : "l"(p));
    return a;
}
static __device__ __forceinline__ void cp16(uint32_t s, const void* g, bool pred) {
    int sz = pred ? 16 : 0;
    asm volatile("cp.async.cg.shared.global [%0], [%1], 16, %2;" :: "r"(s), "l"(g), "r"(sz));
}
#define CP_COMMIT() asm volatile("cp.async.commit_group;" ::: "memory")
#define CP_WAIT2()  asm volatile("cp.async.wait_group 2;"  ::: "memory")

#define LDSM4(r, addr) asm volatile( \
    "ldmatrix.sync.aligned.m8n8.x4.shared.b16 {%0,%1,%2,%3}, [%4];" \
    : "=r"((r)[0]),"=r"((r)[1]),"=r"((r)[2]),"=r"((r)[3]) : "r"(addr))
#define MMA(d, a, b) asm volatile( \
    "mma.sync.aligned.m16n8k16.row.col.f32.f16.f16.f32 " \
    "{%0,%1,%2,%3},{%4,%5,%6,%7},{%8,%9},{%0,%1,%2,%3};" \
    : "+f"((d)[0]),"+f"((d)[1]),"+f"((d)[2]),"+f"((d)[3]) \
    : "r"((a)[0]),"r"((a)[1]),"r"((a)[2]),"r"((a)[3]),"r"((b)[0]),"r"((b)[1]))

// ---------------- embed ----------------
__global__ void k_embed(const int* __restrict__ ids, const float* __restrict__ emb) {
    int t = blockIdx.x;
    int id = ids[t];
    for (int c = threadIdx.x; c < DM; c += blockDim.x)
        g_x[t*DM + c] = emb[id*DM + c];
}

// ---------------- rmsnorm -> fp16 hi/lo split ----------------
__global__ void k_rmsnorm(const float* __restrict__ x, const float* __restrict__ w,
                          __half* __restrict__ oh, __half* __restrict__ ol) {
    int t = blockIdx.x;
    const float* xr = x + t*DM;
    float s = 0.f;
    for (int c = threadIdx.x; c < DM; c += blockDim.x) { float v = xr[c]; s += v*v; }
    for (int o = 16; o > 0; o >>= 1) s += __shfl_xor_sync(0xffffffffu, s, o);
    __shared__ float red[8];
    int wid = threadIdx.x >> 5, lid = threadIdx.x & 31;
    if (lid == 0) red[wid] = s;
    __syncthreads();
    if (wid == 0) {
        float v = (lid < (blockDim.x >> 5)) ? red[lid] : 0.f;
        for (int o = 4; o > 0; o >>= 1) v += __shfl_xor_sync(0xffffffffu, v, o);
        if (lid == 0) red[0] = v;
    }
    __syncthreads();
    float scale = rsqrtf(red[0] / (float)DM + 1e-5f);
    for (int c = threadIdx.x; c < DM; c += blockDim.x) {
        float v = xr[c] * scale * w[c];
        __half h = __float2half_rn(v);
        oh[t*DM + c] = h;
        ol[t*DM + c] = __float2half_rn(v - __half2float(h));
    }
}

// ---------------- fp32 -> fp16 hi/lo split (A-side), 4 elems/thread ----------------
__global__ void k_split(const float* __restrict__ x, __half* __restrict__ h,
                        __half* __restrict__ l, int n) {
    int i = (blockIdx.x * blockDim.x + threadIdx.x) * 4;
    if (i >= n) return;
    float4 v = *reinterpret_cast<const float4*>(x + i);
    __half h0 = __float2half_rn(v.x), h1 = __float2half_rn(v.y);
    __half h2 = __float2half_rn(v.z), h3 = __float2half_rn(v.w);
    __half2 H0, H1, L0, L1;
    H0.x = h0; H0.y = h1; H1.x = h2; H1.y = h3;
    L0.x = __float2half_rn(v.x - __half2float(h0));
    L0.y = __float2half_rn(v.y - __half2float(h1));
    L1.x = __float2half_rn(v.z - __half2float(h2));
    L1.y = __float2half_rn(v.w - __half2float(h3));
    *reinterpret_cast<uint2*>(h + i) =
        make_uint2(*reinterpret_cast<uint32_t*>(&H0), *reinterpret_cast<uint32_t*>(&H1));
    *reinterpret_cast<uint2*>(l + i) =
        make_uint2(*reinterpret_cast<uint32_t*>(&L0), *reinterpret_cast<uint32_t*>(&L1));
}

// ---------------- fp32 -> fp16 plain convert (B-side), 8 elems/thread ----------------
__global__ void k_cvt(const float* __restrict__ x, __half* __restrict__ o, int n) {
    int i = (blockIdx.x * blockDim.x + threadIdx.x) * 8;
    if (i >= n) return;
    float4 a = *reinterpret_cast<const float4*>(x + i);
    float4 b = *reinterpret_cast<const float4*>(x + i + 4);
    __half2 p0, p1, p2, p3;
    p0.x = __float2half_rn(a.x); p0.y = __float2half_rn(a.y);
    p1.x = __float2half_rn(a.z); p1.y = __float2half_rn(a.w);
    p2.x = __float2half_rn(b.x); p2.y = __float2half_rn(b.y);
    p3.x = __float2half_rn(b.z); p3.y = __float2half_rn(b.w);
    uint4 pk;
    pk.x = *reinterpret_cast<uint32_t*>(&p0);
    pk.y = *reinterpret_cast<uint32_t*>(&p1);
    pk.z = *reinterpret_cast<uint32_t*>(&p2);
    pk.w = *reinterpret_cast<uint32_t*>(&p3);
    *reinterpret_cast<uint4*>(o + i) = pk;
}

// ---------------- HMMA GEMM: C[M,N] = A[M,K] @ B[N,K]^T, fp16 2-term ----------------
#define EPI_NONE     0
#define EPI_SOFTPLUS 1
#define EPI_RESADD   2

#define TILE_B   8192          // 128 rows x 64 bytes (BK=32 fp16)
#define OFF_AH   0
#define OFF_AL   (1*TILE_B)
#define OFF_BF   (2*TILE_B)
#define STAGE_B  (3*TILE_B)    // 24 KB
#define NSTAGE   4
#define SMEM_DYN (NSTAGE*STAGE_B)   // 96 KB

__device__ __forceinline__ void load_stage(uint32_t sbase,
        const __half* __restrict__ Ah, const __half* __restrict__ Al,
        int lda, int m0,
        const __half* __restrict__ Bf,
        int ldb, int n0, int N, int k0, int tid) {
    #pragma unroll
    for (int it = 0; it < 2; it++) {
        int i = tid + it*256;
        int r = i >> 2;
        int cby = (i & 3) * 16;
        uint32_t off = r*64 + (cby ^ (((r >> 1) & 3) << 4));
        size_t ga = (size_t)(m0 + r)*lda + k0 + (i & 3)*8;
        cp16(sbase + OFF_AH + off, Ah + ga, true);
        cp16(sbase + OFF_AL + off, Al + ga, true);
        bool bp = (n0 + r) < N;
        size_t gb = (size_t)(bp ? (n0 + r) : 0)*ldb + k0 + (i & 3)*8;
        cp16(sbase + OFF_BF + off, Bf + gb, bp);
    }
}

template<int EPI>
__global__ void __launch_bounds__(256, 2) k_mma(
        const __half* __restrict__ Ah, const __half* __restrict__ Al, int lda,
        const __half* __restrict__ Bf, int ldb,
        float* __restrict__ C, int ldc, int M, int N, int K,
        const float* __restrict__ R) {
    extern __shared__ __align__(1024) char smem[];
    const uint32_t sb = s2u(smem);
    const int tid = threadIdx.x, lane = tid & 31, wid = tid >> 5;
    const int wm = wid >> 2, wn = wid & 3;       // 2 x 4 warp grid
    const int m0 = blockIdx.x * 128, n0 = blockIdx.y * 128;

    float acc[4][4][4];
    #pragma unroll
    for (int a = 0; a < 4; a++)
        #pragma unroll
        for (int b = 0; b < 4; b++)
            #pragma unroll
            for (int c = 0; c < 4; c++) acc[a][b][c] = 0.f;

    const int NC = K / 32;
    #pragma unroll
    for (int p = 0; p < 3; p++) {
        if (p < NC)
            load_stage(sb + p*STAGE_B, Ah, Al, lda, m0, Bf, ldb, n0, N, p*32, tid);
        CP_COMMIT();
    }

    const int arow = lane & 15;
    const int acb  = ((lane >> 4) & 1) * 16;
    const int brow = lane & 7;
    const int bnt  = (lane >> 4) & 1;
    const int bkh  = (lane >> 3) & 1;

    int stage = 0;
    for (int c = 0; c < NC; c++) {
        CP_WAIT2();
        __syncthreads();
        if (c + 3 < NC) {
            int s3 = stage + 3; if (s3 >= NSTAGE) s3 -= NSTAGE;
            load_stage(sb + s3*STAGE_B, Ah, Al, lda, m0, Bf, ldb, n0, N,
                       (c + 3)*32, tid);
        }
        CP_COMMIT();

        uint32_t st = sb + stage*STAGE_B;
        #pragma unroll
        for (int kk = 0; kk < 2; kk++) {
            uint32_t bf[4][2], ah[4][4], al[4][4];
            #pragma unroll
            for (int p = 0; p < 2; p++) {
                int r = wn*32 + (p*2 + bnt)*8 + brow;
                uint32_t off = r*64 + (((kk*2 + bkh)*16) ^ (((r >> 1) & 3) << 4));
                uint32_t t[4];
                LDSM4(t, st + OFF_BF + off);
                bf[2*p][0] = t[0]; bf[2*p][1] = t[1];
                bf[2*p+1][0] = t[2]; bf[2*p+1][1] = t[3];
            }
            #pragma unroll
            for (int mt = 0; mt < 4; mt++) {
                int r = wm*64 + mt*16 + arow;
                uint32_t off = r*64 + ((kk*32 + acb) ^ (((r >> 1) & 3) << 4));
                LDSM4(ah[mt], st + OFF_AH + off);
                LDSM4(al[mt], st + OFF_AL + off);
            }
            #pragma unroll
            for (int mt = 0; mt < 4; mt++)
                #pragma unroll
                for (int nt = 0; nt < 4; nt++)
                    MMA(acc[mt][nt], ah[mt], bf[nt]);
            #pragma unroll
            for (int mt = 0; mt < 4; mt++)
                #pragma unroll
                for (int nt = 0; nt < 4; nt++)
                    MMA(acc[mt][nt], al[mt], bf[nt]);
        }
        stage++; if (stage >= NSTAGE) stage = 0;
    }

    // epilogue
    #pragma unroll
    for (int mt = 0; mt < 4; mt++) {
        #pragma unroll
        for (int nt = 0; nt < 4; nt++) {
            int row = m0 + wm*64 + mt*16 + (lane >> 2);
            int col = n0 + wn*32 + nt*8 + (lane & 3)*2;
            if (col < N) {
                #pragma unroll
                for (int h = 0; h < 2; h++) {
                    int rr = row + h*8;
                    float v0 = acc[mt][nt][2*h + 0];
                    float v1 = acc[mt][nt][2*h + 1];
                    if (EPI == EPI_SOFTPLUS) {
                        v0 = (v0 > 20.f) ? v0 : log1pf(expf(v0));
                        v1 = (v1 > 20.f) ? v1 : log1pf(expf(v1));
                    }
                    if (EPI == EPI_RESADD) {
                        v0 += R[(size_t)rr*ldc + col];
                        v1 += R[(size_t)rr*ldc + col + 1];
                    }
                    *reinterpret_cast<float2*>(&C[(size_t)rr*ldc + col]) = make_float2(v0, v1);
                }
            }
        }
    }
}

// ---------------- depthwise causal conv + bias + SiLU -> u fp32 + fp16 split ----------------
__global__ void k_conv_silu(const float* __restrict__ cw, const float* __restrict__ cb) {
    int idx = blockIdx.x * blockDim.x + threadIdx.x;
    if (idx >= TT*DI) return;
    int d = idx % DI;
    int l = (idx / DI) % LL;
    int b = idx / (DI*LL);
    float acc = cb[d];
    #pragma unroll
    for (int j = 0; j < DC; j++) {
        int ll = l - (DC-1) + j;
        if (ll >= 0) acc = fmaf(cw[d*DC + j], g_xi[((size_t)b*LL + ll)*DI + d], acc);
    }
    float s = acc / (1.f + __expf(-acc));
    g_u[idx] = s;
    __half h = __float2half_rn(s);
    g_u_h[idx] = h;
    g_u_l[idx] = __float2half_rn(s - __half2float(h));
}

// ---------------- selective scan + gate -> y fp16 split ----------------
__global__ void k_scan(const float* __restrict__ A_log, const float* __restrict__ Dp) {
    int lane = threadIdx.x & 15;
    int grp  = threadIdx.x >> 4;
    int ch   = blockIdx.x * 16 + grp;
    int b = ch / DI, d = ch % DI;

    float An = -__expf(A_log[d*DS + lane]);
    float Dv = Dp[d];
    float xs = 0.f;

    for (int l = 0; l < LL; l++) {
        int tok = b*LL + l;
        float dlt = g_dlt[(size_t)tok*DI + d];
        float uu  = g_u  [(size_t)tok*DI + d];
        float Bn  = g_xdbl[(size_t)tok*96 + 64 + lane];
        float Cn  = g_xdbl[(size_t)tok*96 + 80 + lane];
        float dA  = __expf(dlt * An);
        xs = fmaf(dA, xs, dlt * uu * Bn);
        float yv = xs * Cn;
        yv += __shfl_xor_sync(0xffffffffu, yv, 8);
        yv += __shfl_xor_sync(0xffffffffu, yv, 4);
        yv += __shfl_xor_sync(0xffffffffu, yv, 2);
        yv += __shfl_xor_sync(0xffffffffu, yv, 1);
        if (lane == 0) {
            float r = g_res[(size_t)tok*DI + d];
            float gate = r / (1.f + __expf(-r));
            float v = (yv + uu * Dv) * gate;
            __half h = __float2half_rn(v);
            g_y_h[(size_t)tok*DI + d] = h;
            g_y_l[(size_t)tok*DI + d] = __float2half_rn(v - __half2float(h));
        }
    }
}

// ---------------- launch ----------------
extern "C" void kernel_launch(void* const* d_in, const int* in_sizes, int n_in,
                              void* d_out, int out_size) {
    const int*   ids      = (const int*)  d_in[0];
    const float* emb      = (const float*)d_in[1];
    const float* norm_f_w = (const float*)d_in[2];
    const float* W_in_l   = (const float*)d_in[3];
    const float* W_in_r   = (const float*)d_in[4];
    const float* conv_w   = (const float*)d_in[5];
    const float* conv_b   = (const float*)d_in[6];
    const float* W_x      = (const float*)d_in[7];
    const float* W_dt     = (const float*)d_in[8];
    const float* A_log    = (const float*)d_in[9];
    const float* Dp       = (const float*)d_in[10];
    const float* W_out    = (const float*)d_in[11];
    const float* norm_w   = (const float*)d_in[12];
    float* out = (float*)d_out;

    float *p_x, *p_xi, *p_res, *p_u, *p_xdbl, *p_dlt;
    cudaGetSymbolAddress((void**)&p_x,    g_x);
    cudaGetSymbolAddress((void**)&p_xi,   g_xi);
    cudaGetSymbolAddress((void**)&p_res,  g_res);
    cudaGetSymbolAddress((void**)&p_u,    g_u);
    cudaGetSymbolAddress((void**)&p_xdbl, g_xdbl);
    cudaGetSymbolAddress((void**)&p_dlt,  g_dlt);

    __half *p_ef, *p_xnh, *p_xnl, *p_uh, *p_ul, *p_xdh, *p_xdl, *p_yh, *p_yl, *p_wf;
    cudaGetSymbolAddress((void**)&p_ef,  g_emb_f);
    cudaGetSymbolAddress((void**)&p_xnh, g_xn_h);
    cudaGetSymbolAddress((void**)&p_xnl, g_xn_l);
    cudaGetSymbolAddress((void**)&p_uh,  g_u_h);
    cudaGetSymbolAddress((void**)&p_ul,  g_u_l);
    cudaGetSymbolAddress((void**)&p_xdh, g_xd_h);
    cudaGetSymbolAddress((void**)&p_xdl, g_xd_l);
    cudaGetSymbolAddress((void**)&p_yh,  g_y_h);
    cudaGetSymbolAddress((void**)&p_yl,  g_y_l);
    cudaGetSymbolAddress((void**)&p_wf,  g_w_f);

    cudaFuncSetAttribute(k_mma<EPI_NONE>,     cudaFuncAttributeMaxDynamicSharedMemorySize, SMEM_DYN);
    cudaFuncSetAttribute(k_mma<EPI_SOFTPLUS>, cudaFuncAttributeMaxDynamicSharedMemorySize, SMEM_DYN);
    cudaFuncSetAttribute(k_mma<EPI_RESADD>,   cudaFuncAttributeMaxDynamicSharedMemorySize, SMEM_DYN);

    k_embed<<<TT, 256>>>(ids, emb);
    k_cvt<<<(VOCAB*DM/8 + 255)/256, 256>>>(emb, p_ef, VOCAB*DM);

    for (int i = 0; i < NLAYER; i++) {
        const float* Wl  = W_in_l + (size_t)i*DI*DM;
        const float* Wr  = W_in_r + (size_t)i*DI*DM;
        const float* cw  = conv_w + (size_t)i*DI*DC;
        const float* cb  = conv_b + (size_t)i*DI;
        const float* Wx  = W_x    + (size_t)i*(DR+2*DS)*DI;
        const float* Wdt = W_dt   + (size_t)i*DI*DR;
        const float* Al  = A_log  + (size_t)i*DI*DS;
        const float* Dpi = Dp     + (size_t)i*DI;
        const float* Wo  = W_out  + (size_t)i*DM*DI;
        const float* nw  = norm_w + (size_t)i*DM;

        k_rmsnorm<<<TT, 256>>>(p_x, nw, p_xnh, p_xnl);

        // xi = xn @ Wl^T   (2048 x 2048, K=1024)
        k_cvt<<<(DI*DM/8 + 255)/256, 256>>>(Wl, p_wf, DI*DM);
        k_mma<EPI_NONE><<<dim3(TT/128, DI/128), 256, SMEM_DYN>>>(
            p_xnh, p_xnl, DM, p_wf, DM, p_xi, DI, TT, DI, DM, nullptr);

        // res = xn @ Wr^T
        k_cvt<<<(DI*DM/8 + 255)/256, 256>>>(Wr, p_wf, DI*DM);
        k_mma<EPI_NONE><<<dim3(TT/128, DI/128), 256, SMEM_DYN>>>(
            p_xnh, p_xnl, DM, p_wf, DM, p_res, DI, TT, DI, DM, nullptr);

        k_conv_silu<<<(TT*DI + 255)/256, 256>>>(cw, cb);

        // x_dbl = u @ Wx^T  (2048 x 96, K=2048)
        k_cvt<<<(96*DI/8 + 255)/256, 256>>>(Wx, p_wf, 96*DI);
        k_mma<EPI_NONE><<<dim3(TT/128, 1), 256, SMEM_DYN>>>(
            p_uh, p_ul, DI, p_wf, DI, p_xdbl, 96, TT, 96, DI, nullptr);

        k_split<<<(TT*96/4 + 255)/256, 256>>>(p_xdbl, p_xdh, p_xdl, TT*96);

        // delta = softplus(x_dbl[:, :64] @ Wdt^T)  (2048 x 2048, K=64)
        k_cvt<<<(DI*DR/8 + 255)/256, 256>>>(Wdt, p_wf, DI*DR);
        k_mma<EPI_SOFTPLUS><<<dim3(TT/128, DI/128), 256, SMEM_DYN>>>(
            p_xdh, p_xdl, 96, p_wf, DR, p_dlt, DI, TT, DI, DR, nullptr);

        k_scan<<<(BB*DI)/16, 256>>>(Al, Dpi);

        // x = y @ Wo^T + x  (2048 x 1024, K=2048)
        k_cvt<<<(DM*DI/8 + 255)/256, 256>>>(Wo, p_wf, DM*DI);
        k_mma<EPI_RESADD><<<dim3(TT/128, DM/128), 256, SMEM_DYN>>>(
            p_yh, p_yl, DI, p_wf, DI, p_x, DM, TT, DM, DI, p_x);
    }

    // final norm + logits (2048 x 32000, K=1024)
    k_rmsnorm<<<TT, 256>>>(p_x, norm_f_w, p_xnh, p_xnl);
    k_mma<EPI_NONE><<<dim3(TT/128, VOCAB/128), 256, SMEM_DYN>>>(
        p_xnh, p_xnl, DM, p_ef, DM, out, VOCAB, TT, VOCAB, DM, nullptr);
}